// round 9
// baseline (speedup 1.0000x reference)
#include <cuda_runtime.h>
#include <cuda_fp16.h>
#include <math.h>

#define NSTEPS 4096
#define SMEMB 184320
#define B_BIN 0
#define B_SIB 8
#define XBUF 16
#define SIBB 1040
#define GATE 2064
#define PART 4112
#define HSO  20496
#define CSO  21008
#define BIASO 21520
#define GACCO 23568
#define OBUF  25616
#define WOFF  26144

__device__ float g_Ct[8192 * 128];
__device__ float g_pre[4096 * 128];
__device__ float g_b0[128];

typedef unsigned long long u64t;

__device__ __forceinline__ float sigm(float x) { return 1.0f / (1.0f + expf(-x)); }

__device__ __forceinline__ unsigned smem_u32(const void* p) {
    unsigned a; asm("{.reg .u64 t; cvta.to.shared.u64 t,%1; cvt.u32.u64 %0,t;}" : "=r"(a) : "l"(p)); return a;
}
__device__ __forceinline__ unsigned mapa_u32(unsigned l, unsigned rk) {
    unsigned r; asm("mapa.shared::cluster.u32 %0,%1,%2;" : "=r"(r) : "r"(l), "r"(rk)); return r;
}
__device__ __forceinline__ void mb_init(unsigned b, unsigned n) {
    asm volatile("mbarrier.init.shared.b64 [%0],%1;" :: "r"(b), "r"(n) : "memory");
}
__device__ __forceinline__ void bar_arm(unsigned b, unsigned tx) {
    asm volatile("mbarrier.arrive.expect_tx.shared.b64 _,[%0],%1;" :: "r"(b), "r"(tx) : "memory");
}
__device__ __forceinline__ void bar_wait(unsigned b, unsigned ph) {
    asm volatile("{.reg .pred P;\nW%=: mbarrier.try_wait.parity.acquire.cluster.shared::cta.b64 P,[%0],%1;\n@!P bra W%=;}\n"
                 :: "r"(b), "r"(ph) : "memory");
}
__device__ __forceinline__ void st_async2(unsigned ra, float x, float y, unsigned rb) {
    u64t v = (u64t)__float_as_uint(x) | ((u64t)__float_as_uint(y) << 32);
    asm volatile("st.async.shared::cluster.mbarrier::complete_tx::bytes.b64 [%0],%1,[%2];"
                 :: "r"(ra), "l"(v), "r"(rb) : "memory");
}
__device__ __forceinline__ void csync() {
    asm volatile("barrier.cluster.arrive.aligned;\nbarrier.cluster.wait.aligned;" ::: "memory");
}

// packed-f32x2 dot: NP packed weight regs vs x[c0..c0+2*NP) in smem
template<int NP>
__device__ __forceinline__ float dotp(const u64t* w, const float* x, int c0) {
    u64t acc = 0;
#pragma unroll
    for (int j = 0; j < NP; j++) {
        u64t xv = *(const u64t*)(x + c0 + 2 * j);
        asm("fma.rn.f32x2 %0,%1,%2,%0;" : "+l"(acc) : "l"(w[j]), "l"(xv));
    }
    float2 a = *(float2*)&acc;
    return a.x + a.y;
}

// fp16 matvec (off-critical-path): R rows x 128 cols, 512 threads
template<int R>
__device__ __forceinline__ void mvh(const __half2* __restrict__ W, const float* __restrict__ x,
                                    float* __restrict__ part, int tid) {
    constexpr int RP = R / 64;
    int rq = tid & 63, p = tid >> 6;
    float acc[RP];
#pragma unroll
    for (int i = 0; i < RP; i++) acc[i] = 0.f;
#pragma unroll
    for (int k = 0; k < 8; k++) {
        int c2 = p * 8 + k;
        float2 xf = *(const float2*)(x + 2 * c2);
        const __half2* wp = W + c2 * R + rq * RP;
#pragma unroll
        for (int i = 0; i < RP; i++) {
            float2 wf = __half22float2(wp[i]);
            acc[i] += wf.x * xf.x + wf.y * xf.y;
        }
    }
#pragma unroll
    for (int i = 0; i < RP; i++) part[p * R + rq * RP + i] = acc[i];
}
__device__ __forceinline__ float redp(const float* part, int R, int r) {
    float s = 0.f;
#pragma unroll
    for (int p = 0; p < 8; p++) s += part[p * R + r];
    return s;
}

// ---------- precompute ----------
__global__ void k_bias0(const float* __restrict__ Wi2h, const float* __restrict__ bi2h,
                        const float* __restrict__ bs2i) {
    int h = threadIdx.x;
    float s = bi2h[h];
    for (int e = 0; e < 1024; e++) s += Wi2h[h * 1152 + e] * bs2i[e];
    g_b0[h] = s;
}
__global__ void __launch_bounds__(256) k_ct(const float* __restrict__ Wi2h,
                                            const float* __restrict__ Ws2i) {
    __shared__ float wa[32 * 128];
    int d0 = blockIdx.x * 64, dl = threadIdx.x & 63, hq = threadIdx.x >> 6;
    float acc[32];
#pragma unroll
    for (int k = 0; k < 32; k++) acc[k] = 0.f;
    for (int e0 = 0; e0 < 1024; e0 += 32) {
        __syncthreads();
        for (int i = threadIdx.x; i < 4096; i += 256)
            wa[i] = Wi2h[(i & 127) * 1152 + e0 + (i >> 7)];
        __syncthreads();
#pragma unroll 4
        for (int j = 0; j < 32; j++) {
            float s = Ws2i[(e0 + j) * 8192 + d0 + dl];
            const float* wr = wa + j * 128 + hq * 32;
#pragma unroll
            for (int k = 0; k < 32; k++) acc[k] += wr[k] * s;
        }
    }
    float* dst = g_Ct + (d0 + dl) * 128 + hq * 32;
#pragma unroll
    for (int k = 0; k < 32; k++) dst[k] = acc[k];
}
__global__ void __launch_bounds__(256) k_pre(const float* __restrict__ inputs) {
    __shared__ float in_s[16 * 128];
    int t0 = blockIdx.x * 16, h = threadIdx.x & 127, tq = threadIdx.x >> 7;
    float acc[8];
#pragma unroll
    for (int u = 0; u < 8; u++) acc[u] = 0.f;
    for (int d0 = 0; d0 < 8192; d0 += 128) {
        __syncthreads();
        for (int i = threadIdx.x; i < 2048; i += 256)
            in_s[i] = inputs[(t0 + (i >> 7)) * 8192 + d0 + (i & 127)];
        __syncthreads();
#pragma unroll 2
        for (int dd = 0; dd < 128; dd++) {
            float ctv = g_Ct[(d0 + dd) * 128 + h];
#pragma unroll
            for (int u = 0; u < 8; u++) acc[u] += in_s[(tq * 8 + u) * 128 + dd] * ctv;
        }
    }
    float b = g_b0[h];
#pragma unroll
    for (int u = 0; u < 8; u++) g_pre[(t0 + tq * 8 + u) * 128 + h] = acc[u] + b;
}

// ---------- persistent cluster stages ----------
__device__ void lstm0(char* smc, unsigned sb, const float* Wih, const float* Whh,
                      const float* bih, const float* bhh, const float* out0,
                      const float* h0g, const float* c0g, float* dout, int out_size, int tid) {
    float* xb = (float*)(smc + XBUF);
    float* sib = (float*)(smc + SIBB);
    float* gates = (float*)(smc + GATE);
    float* part = (float*)(smc + PART);
    float* hS = (float*)(smc + HSO);
    float* cS = (float*)(smc + CSO);
    float* bias = (float*)(smc + BIASO);
    float* gacc = (float*)(smc + GACCO);
    float* wih = (float*)(smc + WOFF);               // 512x12 fp32 pad13
    __half2* whh = (__half2*)(smc + WOFF + 26624);   // 64 x 512 half2

    for (int i = tid; i < 512 * 12; i += 512) { int lr = i / 12, j = i - lr * 12; wih[lr * 13 + j] = Wih[lr * 12 + j]; }
    for (int i = tid; i < 64 * 512; i += 512) {
        int c2 = i >> 9, lr = i & 511;
        float2 a = *(const float2*)(Whh + lr * 128 + 2 * c2);
        whh[c2 * 512 + lr] = __floats2half2_rn(a.x, a.y);
    }
    bias[tid] = bih[tid] + bhh[tid];
    if (tid < 128) { sib[128 + tid] = h0g[tid]; hS[tid] = h0g[tid]; cS[tid] = c0g[tid]; }
    if (tid < 12) xb[tid] = out0[tid];
    if (tid == 0) mb_init(sb + B_BIN, 1);
    __syncthreads();
    mvh<512>(whh, sib + 128, part, tid);
    __syncthreads();
    gacc[tid] = redp(part, 512, tid);
    if (tid == 0) asm volatile("fence.mbarrier_init.release.cluster;" ::: "memory");
    csync();
    unsigned r1 = mapa_u32(sb, 1), r2 = mapa_u32(sb, 2);

    for (int t = 0; t < NSTEPS; t++) {
        int par = t & 1;
        if (t > 0) { if (tid == 0) { bar_arm(sb + B_BIN, 48); bar_wait(sb + B_BIN, (t - 1) & 1); } }
        __syncthreads();
        const float* x = (const float*)(smc + XBUF) + par * 16;
        {
            const float* w = wih + tid * 13;
            float g = bias[tid] + gacc[tid];
#pragma unroll
            for (int j = 0; j < 12; j++) g += w[j] * x[j];
            gates[tid] = g;
        }
        __syncthreads();
        if (tid < 128) {
            float cn = sigm(gates[128 + tid]) * cS[tid] + sigm(gates[tid]) * tanhf(gates[256 + tid]);
            float hn = sigm(gates[384 + tid]) * tanhf(cn);
            cS[tid] = cn; hS[tid] = hn;
            sib[par * 128 + tid] = hn;
            float pv = __shfl_xor_sync(0xffffffffu, hn, 1);
            if (!(tid & 1)) {
                unsigned o4 = XBUF + par * 512 + tid * 4;
                st_async2(r1 + o4, hn, pv, r1 + B_BIN);
                st_async2(r2 + o4, hn, pv, r2 + B_BIN);
            }
        }
        __syncthreads();
        if (t < NSTEPS - 1) {
            mvh<512>(whh, sib + par * 128, part, tid);
            __syncthreads();
            gacc[tid] = redp(part, 512, tid);
            __syncthreads();
        }
    }
    if (out_size >= 49920 && tid < 128) { dout[49152 + tid] = hS[tid]; dout[49536 + tid] = cS[tid]; }
    csync();
}

__device__ void lstm_mid(char* smc, unsigned sb, int l, int half, int sibrank,
                         int c0r, int c1r, int ncons,
                         const float* Wih, const float* Whh, const float* bih, const float* bhh,
                         const float* h0g, const float* c0g, float* dout, int out_size, int tid) {
    float* xb = (float*)(smc + XBUF);
    float* sib = (float*)(smc + SIBB);
    float* gates = (float*)(smc + GATE);
    float* part = (float*)(smc + PART);
    float* hS = (float*)(smc + HSO);
    float* cS = (float*)(smc + CSO);
    float* bias = (float*)(smc + BIASO);
    float* gacc = (float*)(smc + GACCO);
    __half2* whh = (__half2*)(smc + WOFF);   // 64 x 256 half2
    const int U0 = half * 64;
    const int row = tid >> 1, sub = tid & 1;
    const int grow = (row >> 6) * 128 + U0 + (row & 63);

    u64t wr[32];                             // Wih row-half, packed fp32 pairs
#pragma unroll
    for (int j = 0; j < 32; j++) wr[j] = *(const u64t*)(Wih + grow * 128 + sub * 64 + 2 * j);

    for (int i = tid; i < 64 * 256; i += 512) {
        int c2 = i >> 8, lr = i & 255;
        int gr = (lr >> 6) * 128 + U0 + (lr & 63);
        float2 b = *(const float2*)(Whh + gr * 128 + 2 * c2);
        whh[c2 * 256 + lr] = __floats2half2_rn(b.x, b.y);
    }
    if (tid < 256) { int gr = (tid >> 6) * 128 + U0 + (tid & 63); bias[tid] = bih[gr] + bhh[gr]; }
    if (tid < 128) sib[128 + tid] = h0g[tid];
    if (tid < 64) { hS[tid] = h0g[U0 + tid]; cS[tid] = c0g[U0 + tid]; }
    if (tid == 0) { mb_init(sb + B_BIN, 1); mb_init(sb + B_SIB, 1); }
    __syncthreads();
    mvh<256>(whh, sib + 128, part, tid);
    __syncthreads();
    if (tid < 256) gacc[tid] = redp(part, 256, tid);
    if (tid == 0) asm volatile("fence.mbarrier_init.release.cluster;" ::: "memory");
    csync();
    unsigned rs = mapa_u32(sb, sibrank);
    unsigned rc0 = mapa_u32(sb, c0r);
    unsigned rc1 = (ncons > 1) ? mapa_u32(sb, c1r) : 0;

    for (int t = 0; t < NSTEPS; t++) {
        int par = t & 1;
        if (tid == 0) { bar_arm(sb + B_BIN, 512); bar_wait(sb + B_BIN, par); }
        __syncthreads();
        {
            float s = dotp<32>(wr, xb + par * 128, sub * 64);
            s += __shfl_xor_sync(0xffffffffu, s, 1);
            if (!sub) gates[row] = s + bias[row] + gacc[row];
        }
        __syncthreads();
        if (tid < 64) {
            float cn = sigm(gates[64 + tid]) * cS[tid] + sigm(gates[tid]) * tanhf(gates[128 + tid]);
            float hn = sigm(gates[192 + tid]) * tanhf(cn);
            cS[tid] = cn; hS[tid] = hn;
            sib[par * 128 + U0 + tid] = hn;
            float pv = __shfl_xor_sync(0xffffffffu, hn, 1);
            if (!(tid & 1)) {
                unsigned o4 = (U0 + tid) * 4;
                if (t < NSTEPS - 1) st_async2(rs + SIBB + par * 512 + o4, hn, pv, rs + B_SIB);
                st_async2(rc0 + XBUF + par * 512 + o4, hn, pv, rc0 + B_BIN);
                if (ncons > 1) st_async2(rc1 + XBUF + par * 512 + o4, hn, pv, rc1 + B_BIN);
            }
        }
        if (t < NSTEPS - 1) {
            if (tid == 0) { bar_arm(sb + B_SIB, 256); bar_wait(sb + B_SIB, par); }
            __syncthreads();
            mvh<256>(whh, sib + par * 128, part, tid);
            __syncthreads();
            if (tid < 256) gacc[tid] = redp(part, 256, tid);
            __syncthreads();
        }
    }
    if (out_size >= 49920 && tid < 64) {
        dout[49152 + l * 128 + U0 + tid] = hS[tid];
        dout[49536 + l * 128 + U0 + tid] = cS[tid];
    }
    csync();
}

__device__ void tail(char* smc, unsigned sb, const float* Wi2h, const float* Wh2h,
                     const float* bh2h, const float* Wh2o, const float* bh2o,
                     float* dout, int tid) {
    float* xb = (float*)(smc + XBUF);
    float* h1 = (float*)(smc + GATE);
    float* h2 = (float*)(smc + GATE) + 128;
    float* pres = (float*)(smc + GATE) + 256;
    float* bh = (float*)(smc + BIASO);
    float* bo = (float*)(smc + BIASO) + 128;
    float* obuf = (float*)(smc + OBUF);
    float* wo = (float*)(smc + WOFF);  // 12x128 fp32
    const int row = tid >> 2, sub = tid & 3;

    u64t wa[16], wb[16];
#pragma unroll
    for (int j = 0; j < 16; j++) {
        wa[j] = *(const u64t*)(Wi2h + row * 1152 + 1024 + sub * 32 + 2 * j);
        wb[j] = *(const u64t*)(Wh2h + row * 128 + sub * 32 + 2 * j);
    }
    for (int i = tid; i < 1536; i += 512) wo[i] = Wh2o[i];
    if (tid < 128) bh[tid] = bh2h[tid];
    if (tid < 12) bo[tid] = bh2o[tid];
    if (tid == 0) { mb_init(sb + B_BIN, 1); asm volatile("fence.mbarrier_init.release.cluster;" ::: "memory"); }
    __syncthreads();
    csync();
    unsigned r0 = mapa_u32(sb, 0);

    for (int t = 0; t < NSTEPS; t++) {
        int par = t & 1;
        if (tid < 128) pres[tid] = g_pre[t * 128 + tid];  // overlaps wait
        if (tid == 0) { bar_arm(sb + B_BIN, 512); bar_wait(sb + B_BIN, par); }
        __syncthreads();
        {
            float s = dotp<16>(wa, xb + par * 128, sub * 32);
            s += __shfl_xor_sync(0xffffffffu, s, 1);
            s += __shfl_xor_sync(0xffffffffu, s, 2);
            if (!sub) h1[row] = tanhf(pres[row] + s);
        }
        __syncthreads();
        {
            float s = dotp<16>(wb, h1, sub * 32);
            s += __shfl_xor_sync(0xffffffffu, s, 1);
            s += __shfl_xor_sync(0xffffffffu, s, 2);
            if (!sub) h2[row] = fmaxf(bh[row] + s, 0.f);
        }
        __syncthreads();
        {
            float s = dotp<16>(wb, h2, sub * 32);
            s += __shfl_xor_sync(0xffffffffu, s, 1);
            s += __shfl_xor_sync(0xffffffffu, s, 2);
            if (!sub) h1[row] = fmaxf(bh[row] + s, 0.f);
        }
        __syncthreads();
        int w = tid >> 5, lane = tid & 31;
        if (w < 12) {
            const float* rw = wo + w * 128;
            float s = rw[lane] * h1[lane] + rw[lane + 32] * h1[lane + 32] +
                      rw[lane + 64] * h1[lane + 64] + rw[lane + 96] * h1[lane + 96];
#pragma unroll
            for (int d = 16; d > 0; d >>= 1) s += __shfl_xor_sync(0xffffffffu, s, d);
            if (lane == 0) {
                float o = sigm(s + bo[w]);
                dout[t * 12 + w] = o;
                obuf[w] = o;
            }
        }
        __syncthreads();
        if (t < NSTEPS - 1 && tid < 6)
            st_async2(r0 + XBUF + ((t + 1) & 1) * 64 + tid * 8, obuf[2 * tid], obuf[2 * tid + 1], r0 + B_BIN);
    }
    csync();
}

__global__ void __launch_bounds__(512, 1) __cluster_dims__(6, 1, 1) k_rnn(
    const float* Wih0, const float* Whh0, const float* bih0, const float* bhh0,
    const float* Wih1, const float* Whh1, const float* bih1, const float* bhh1,
    const float* Wih2, const float* Whh2, const float* bih2, const float* bhh2,
    const float* Wi2h, const float* Wh2h, const float* bh2h,
    const float* Wh2o, const float* bh2o, const float* out0,
    const float* h0, const float* c0, float* dout, int out_size) {
    extern __shared__ char smc[];
    unsigned sb = smem_u32(smc);
    int r = blockIdx.x, tid = threadIdx.x;
    if (r == 0)
        lstm0(smc, sb, Wih0, Whh0, bih0, bhh0, out0, h0, c0, dout, out_size, tid);
    else if (r <= 2)
        lstm_mid(smc, sb, 1, r - 1, 3 - r, 3, 4, 2, Wih1, Whh1, bih1, bhh1,
                 h0 + 128, c0 + 128, dout, out_size, tid);
    else if (r <= 4)
        lstm_mid(smc, sb, 2, r - 3, 7 - r, 5, 5, 1, Wih2, Whh2, bih2, bhh2,
                 h0 + 256, c0 + 256, dout, out_size, tid);
    else
        tail(smc, sb, Wi2h, Wh2h, bh2h, Wh2o, bh2o, dout, tid);
}

extern "C" void kernel_launch(void* const* d_in, const int* in_sizes, int n_in,
                              void* d_out, int out_size) {
    const float* output0 = (const float*)d_in[1];
    const float* h0 = (const float*)d_in[2];
    const float* c0 = (const float*)d_in[3];
    const float* Ws2i = (const float*)d_in[4];
    const float* bs2i = (const float*)d_in[5];
    const float* Wi2h = (const float*)d_in[6];
    const float* bi2h = (const float*)d_in[7];
    const float* Wh2h = (const float*)d_in[8];
    const float* bh2h = (const float*)d_in[9];
    const float* Wh2o = (const float*)d_in[10];
    const float* bh2o = (const float*)d_in[11];
    float* out = (float*)d_out;

    static int once = 0;
    if (!once) {
        cudaFuncSetAttribute(k_rnn, cudaFuncAttributeMaxDynamicSharedMemorySize, SMEMB);
        once = 1;
    }
    k_bias0<<<1, 128>>>(Wi2h, bi2h, bs2i);
    k_ct<<<128, 256>>>(Wi2h, (const float*)d_in[4]);
    k_pre<<<256, 256>>>((const float*)d_in[0]);
    k_rnn<<<6, 512, SMEMB>>>(
        (const float*)d_in[12], (const float*)d_in[13], (const float*)d_in[14], (const float*)d_in[15],
        (const float*)d_in[16], (const float*)d_in[17], (const float*)d_in[18], (const float*)d_in[19],
        (const float*)d_in[20], (const float*)d_in[21], (const float*)d_in[22], (const float*)d_in[23],
        Wi2h, Wh2h, bh2h, Wh2o, bh2o, output0, h0, c0, out, out_size);
}

// round 10
// speedup vs baseline: 1.5359x; 1.5359x over previous
#include <cuda_runtime.h>
#include <cuda_fp16.h>
#include <math.h>

#define NSTEPS 4096
#define SMEMB 219136
#define B_BIN 0
#define B_SIB 8
#define XBUF 16
#define SIBB 1040
#define GC0  2064
#define GATE 6160
#define PART 8208
#define HSO  16400
#define CSO  16912
#define BIASO 17424
#define GACCO 19472
#define OBUF 21520
#define BH2  21584
#define BO2  22096
#define WOFF 22160

__device__ float g_Ct[8192 * 128];
__device__ float g_pre[4096 * 128];
__device__ float g_b0[128];

typedef unsigned long long u64t;

__device__ __forceinline__ float sigm(float x) { return 1.0f / (1.0f + expf(-x)); }

__device__ __forceinline__ unsigned smem_u32(const void* p) {
    unsigned a; asm("{.reg .u64 t; cvta.to.shared.u64 t,%1; cvt.u32.u64 %0,t;}" : "=r"(a) : "l"(p)); return a;
}
__device__ __forceinline__ unsigned mapa_u32(unsigned l, unsigned rk) {
    unsigned r; asm("mapa.shared::cluster.u32 %0,%1,%2;" : "=r"(r) : "r"(l), "r"(rk)); return r;
}
__device__ __forceinline__ void mb_init(unsigned b, unsigned n) {
    asm volatile("mbarrier.init.shared.b64 [%0],%1;" :: "r"(b), "r"(n) : "memory");
}
__device__ __forceinline__ void bar_arm(unsigned b, unsigned tx) {
    asm volatile("mbarrier.arrive.expect_tx.shared.b64 _,[%0],%1;" :: "r"(b), "r"(tx) : "memory");
}
// cta-scope acquire: data lands in OUR smem, cluster-scope acquire (~490cyc) unneeded
__device__ __forceinline__ void bar_wait(unsigned b, unsigned ph) {
    asm volatile("{.reg .pred P;\nW%=: mbarrier.try_wait.parity.acquire.cta.shared::cta.b64 P,[%0],%1;\n@!P bra W%=;}\n"
                 :: "r"(b), "r"(ph) : "memory");
}
__device__ __forceinline__ void st_async2(unsigned ra, float x, float y, unsigned rb) {
    u64t v = (u64t)__float_as_uint(x) | ((u64t)__float_as_uint(y) << 32);
    asm volatile("st.async.shared::cluster.mbarrier::complete_tx::bytes.b64 [%0],%1,[%2];"
                 :: "r"(ra), "l"(v), "r"(rb) : "memory");
}
__device__ __forceinline__ void st_dsmem(unsigned ra, float v) {
    asm volatile("st.shared::cluster.f32 [%0],%1;" :: "r"(ra), "f"(v) : "memory");
}
__device__ __forceinline__ void csync() {
    asm volatile("barrier.cluster.arrive.aligned;\nbarrier.cluster.wait.aligned;" ::: "memory");
}

// fp16 matvec: R rows x 128 cols, 512 threads, 4(or 2) independent accumulators/thread
template<int R>
__device__ __forceinline__ void mvh(const __half2* __restrict__ W, const float* __restrict__ x,
                                    float* __restrict__ part, int tid) {
    constexpr int RP = R / 64;
    int rq = tid & 63, p = tid >> 6;
    float acc[RP];
#pragma unroll
    for (int i = 0; i < RP; i++) acc[i] = 0.f;
#pragma unroll
    for (int k = 0; k < 8; k++) {
        int c2 = p * 8 + k;
        float2 xf = *(const float2*)(x + 2 * c2);
        const __half2* wp = W + c2 * R + rq * RP;
#pragma unroll
        for (int i = 0; i < RP; i++) {
            float2 wf = __half22float2(wp[i]);
            acc[i] += wf.x * xf.x + wf.y * xf.y;
        }
    }
#pragma unroll
    for (int i = 0; i < RP; i++) part[p * R + rq * RP + i] = acc[i];
}
__device__ __forceinline__ float redp(const float* part, int R, int r) {
    float s = 0.f;
#pragma unroll
    for (int p = 0; p < 8; p++) s += part[p * R + r];
    return s;
}

// ---------- precompute ----------
__global__ void k_bias0(const float* __restrict__ Wi2h, const float* __restrict__ bi2h,
                        const float* __restrict__ bs2i) {
    int h = threadIdx.x;
    float s = bi2h[h];
    for (int e = 0; e < 1024; e++) s += Wi2h[h * 1152 + e] * bs2i[e];
    g_b0[h] = s;
}
__global__ void __launch_bounds__(256) k_ct(const float* __restrict__ Wi2h,
                                            const float* __restrict__ Ws2i) {
    __shared__ float wa[32 * 128];
    int d0 = blockIdx.x * 64, dl = threadIdx.x & 63, hq = threadIdx.x >> 6;
    float acc[32];
#pragma unroll
    for (int k = 0; k < 32; k++) acc[k] = 0.f;
    for (int e0 = 0; e0 < 1024; e0 += 32) {
        __syncthreads();
        for (int i = threadIdx.x; i < 4096; i += 256)
            wa[i] = Wi2h[(i & 127) * 1152 + e0 + (i >> 7)];
        __syncthreads();
#pragma unroll 4
        for (int j = 0; j < 32; j++) {
            float s = Ws2i[(e0 + j) * 8192 + d0 + dl];
            const float* wr = wa + j * 128 + hq * 32;
#pragma unroll
            for (int k = 0; k < 32; k++) acc[k] += wr[k] * s;
        }
    }
    float* dst = g_Ct + (d0 + dl) * 128 + hq * 32;
#pragma unroll
    for (int k = 0; k < 32; k++) dst[k] = acc[k];
}
__global__ void __launch_bounds__(256) k_pre(const float* __restrict__ inputs) {
    __shared__ float in_s[16 * 128];
    int t0 = blockIdx.x * 16, h = threadIdx.x & 127, tq = threadIdx.x >> 7;
    float acc[8];
#pragma unroll
    for (int u = 0; u < 8; u++) acc[u] = 0.f;
    for (int d0 = 0; d0 < 8192; d0 += 128) {
        __syncthreads();
        for (int i = threadIdx.x; i < 2048; i += 256)
            in_s[i] = inputs[(t0 + (i >> 7)) * 8192 + d0 + (i & 127)];
        __syncthreads();
#pragma unroll 2
        for (int dd = 0; dd < 128; dd++) {
            float ctv = g_Ct[(d0 + dd) * 128 + h];
#pragma unroll
            for (int u = 0; u < 8; u++) acc[u] += in_s[(tq * 8 + u) * 128 + dd] * ctv;
        }
    }
    float b = g_b0[h];
#pragma unroll
    for (int u = 0; u < 8; u++) g_pre[(t0 + tq * 8 + u) * 128 + h] = acc[u] + b;
}

// ---------- persistent cluster stages ----------
// ranks 0,1 = LSTM1 halves (also host Whh0 and produce gacc0 for tail)
// ranks 2,3 = LSTM2 halves; rank 4 = tail MLP + inline LSTM0
__device__ void lstm_mid(char* smc, unsigned sb, int l, int half, int sibrank,
                         int c0r, int c1r, int ncons, int duty,
                         const float* Wih, const float* Whh, const float* bih, const float* bhh,
                         const float* Whh0, const float* h0all,
                         const float* hLg, const float* cLg, float* dout, int out_size, int tid) {
    float* xb = (float*)(smc + XBUF);
    float* sib = (float*)(smc + SIBB);
    float* gates = (float*)(smc + GATE);
    float* part = (float*)(smc + PART);
    float* hS = (float*)(smc + HSO);
    float* cS = (float*)(smc + CSO);
    float* bias = (float*)(smc + BIASO);
    float* gacc = (float*)(smc + GACCO);
    __half2* wih = (__half2*)(smc + WOFF);
    __half2* whh = (__half2*)(smc + WOFF + 65536);
    __half2* w0h = (__half2*)(smc + WOFF + 131072);
    const int U0 = half * 64;

    for (int i = tid; i < 64 * 256; i += 512) {
        int c2 = i >> 8, lr = i & 255;
        int gr = (lr >> 6) * 128 + U0 + (lr & 63);
        wih[i] = __floats2half2_rn(Wih[gr * 128 + 2 * c2], Wih[gr * 128 + 2 * c2 + 1]);
        whh[i] = __floats2half2_rn(Whh[gr * 128 + 2 * c2], Whh[gr * 128 + 2 * c2 + 1]);
        if (duty) {
            int g0r = half * 256 + lr;
            w0h[i] = __floats2half2_rn(Whh0[g0r * 128 + 2 * c2], Whh0[g0r * 128 + 2 * c2 + 1]);
        }
    }
    if (tid < 256) { int gr = (tid >> 6) * 128 + U0 + (tid & 63); bias[tid] = bih[gr] + bhh[gr]; }
    if (tid < 128) sib[128 + tid] = hLg[tid];
    if (tid < 64) { hS[tid] = hLg[U0 + tid]; cS[tid] = cLg[U0 + tid]; }
    if (tid == 0) { mb_init(sb + B_BIN, 1); mb_init(sb + B_SIB, 1); }
    __syncthreads();
    mvh<256>(whh, sib + 128, part, tid);
    __syncthreads();
    if (tid < 256) gacc[tid] = redp(part, 256, tid);
    __syncthreads();
    unsigned rt = mapa_u32(sb, 4);
    if (duty) {
        if (tid < 128) gates[tid] = h0all[tid];
        __syncthreads();
        mvh<256>(w0h, gates, part, tid);
        __syncthreads();
        if (tid < 256) st_dsmem(rt + GC0 + (half * 256 + tid) * 4, redp(part, 256, tid));
    }
    if (tid == 0) asm volatile("fence.mbarrier_init.release.cluster;" ::: "memory");
    csync();
    unsigned rs = mapa_u32(sb, sibrank), rc0 = mapa_u32(sb, c0r);
    unsigned rc1 = (ncons > 1) ? mapa_u32(sb, c1r) : 0;

    for (int t = 0; t < NSTEPS; t++) {
        int par = t & 1;
        if (tid == 0) { bar_arm(sb + B_BIN, 512); bar_wait(sb + B_BIN, par); }
        __syncthreads();
        mvh<256>(wih, xb + par * 128, part, tid);
        __syncthreads();
        if (tid < 256) gates[tid] = bias[tid] + gacc[tid] + redp(part, 256, tid);
        __syncthreads();
        if (tid < 64) {
            float cn = sigm(gates[64 + tid]) * cS[tid] + sigm(gates[tid]) * tanhf(gates[128 + tid]);
            float hn = sigm(gates[192 + tid]) * tanhf(cn);
            cS[tid] = cn; hS[tid] = hn;
            sib[par * 128 + U0 + tid] = hn;
            float pv = __shfl_xor_sync(0xffffffffu, hn, 1);
            if (!(tid & 1)) {
                unsigned o4 = (U0 + tid) * 4;
                if (t < NSTEPS - 1) st_async2(rs + SIBB + par * 512 + o4, hn, pv, rs + B_SIB);
                st_async2(rc0 + XBUF + par * 512 + o4, hn, pv, rc0 + B_BIN);
                if (ncons > 1) st_async2(rc1 + XBUF + par * 512 + o4, hn, pv, rc1 + B_BIN);
            }
        }
        if (duty) {  // gacc0(t+1) = Whh0 @ h0(t); xb[par] still holds h0(t)
            __syncthreads();
            mvh<256>(w0h, xb + par * 128, part, tid);
            __syncthreads();
            if (tid < 256) {
                float v = redp(part, 256, tid);
                float pv = __shfl_xor_sync(0xffffffffu, v, 1);
                if (!(tid & 1))
                    st_async2(rt + GC0 + ((t + 1) & 1) * 2048 + (half * 256 + tid) * 4, v, pv, rt + B_BIN);
            }
        }
        if (t < NSTEPS - 1) {
            if (tid == 0) { bar_arm(sb + B_SIB, 256); bar_wait(sb + B_SIB, par); }
            __syncthreads();
            mvh<256>(whh, sib + par * 128, part, tid);
            __syncthreads();
            if (tid < 256) gacc[tid] = redp(part, 256, tid);
            __syncthreads();
        }
    }
    if (out_size >= 49920 && tid < 64) {
        dout[49152 + l * 128 + U0 + tid] = hS[tid];
        dout[49536 + l * 128 + U0 + tid] = cS[tid];
    }
    csync();
}

__device__ void tail(char* smc, unsigned sb,
                     const float* Wih0, const float* bih0, const float* bhh0,
                     const float* Wi2h, const float* Wh2h, const float* bh2h,
                     const float* Wh2o, const float* bh2o, const float* out0,
                     const float* h0g, const float* c0g, float* dout, int out_size, int tid) {
    float* xb = (float*)(smc + XBUF);
    float* gc0 = (float*)(smc + GC0);
    float* h1 = (float*)(smc + GATE);
    float* h2 = (float*)(smc + GATE) + 128;
    float* pres = (float*)(smc + GATE) + 256;
    float* part = (float*)(smc + PART);
    float* hS = (float*)(smc + HSO);
    float* cS = (float*)(smc + CSO);
    float* bias0 = (float*)(smc + BIASO);
    float* g0 = (float*)(smc + GACCO);
    float* obuf = (float*)(smc + OBUF);
    float* bh = (float*)(smc + BH2);
    float* bo = (float*)(smc + BO2);
    float* wih0 = (float*)(smc + WOFF);
    __half2* wa = (__half2*)(smc + WOFF + 26624);
    __half2* wb = (__half2*)(smc + WOFF + 59392);
    float* wo = (float*)(smc + WOFF + 92160);

    for (int i = tid; i < 512 * 12; i += 512) { int lr = i / 12, j = i - lr * 12; wih0[lr * 13 + j] = Wih0[lr * 12 + j]; }
    for (int i = tid; i < 64 * 128; i += 512) {
        int c2 = i >> 7, lr = i & 127;
        wa[i] = __floats2half2_rn(Wi2h[lr * 1152 + 1024 + 2 * c2], Wi2h[lr * 1152 + 1024 + 2 * c2 + 1]);
        wb[i] = __floats2half2_rn(Wh2h[lr * 128 + 2 * c2], Wh2h[lr * 128 + 2 * c2 + 1]);
    }
    for (int i = tid; i < 1536; i += 512) wo[i] = Wh2o[i];
    bias0[tid] = bih0[tid] + bhh0[tid];
    if (tid < 128) { bh[tid] = bh2h[tid]; hS[tid] = h0g[tid]; cS[tid] = c0g[tid]; }
    if (tid < 12) { bo[tid] = bh2o[tid]; obuf[tid] = out0[tid]; }
    if (tid == 0) { mb_init(sb + B_BIN, 1); asm volatile("fence.mbarrier_init.release.cluster;" ::: "memory"); }
    __syncthreads();
    csync();
    unsigned r0 = mapa_u32(sb, 0), r1 = mapa_u32(sb, 1);
    // pre-loop L0 step 0 -> h0(0); gacc0(0) was direct-written by L1 before csync
    {
        const float* w = wih0 + tid * 13;
        float g = bias0[tid] + gc0[tid];
#pragma unroll
        for (int j = 0; j < 12; j++) g += w[j] * obuf[j];
        g0[tid] = g;
    }
    __syncthreads();
    if (tid < 128) {
        float cn = sigm(g0[128 + tid]) * cS[tid] + sigm(g0[tid]) * tanhf(g0[256 + tid]);
        float hn = sigm(g0[384 + tid]) * tanhf(cn);
        cS[tid] = cn; hS[tid] = hn;
        float pv = __shfl_xor_sync(0xffffffffu, hn, 1);
        if (!(tid & 1)) {
            st_async2(r0 + XBUF + tid * 4, hn, pv, r0 + B_BIN);
            st_async2(r1 + XBUF + tid * 4, hn, pv, r1 + B_BIN);
        }
    }
    for (int t = 0; t < NSTEPS; t++) {
        int par = t & 1;
        float pf = (tid < 128) ? g_pre[t * 128 + tid] : 0.f;  // LDG overlaps wait
        if (tid == 0) { bar_arm(sb + B_BIN, 2560); bar_wait(sb + B_BIN, par); }
        if (tid < 128) pres[tid] = pf;
        __syncthreads();
        mvh<128>(wa, xb + par * 128, part, tid);
        __syncthreads();
        if (tid < 128) h1[tid] = tanhf(pres[tid] + redp(part, 128, tid));
        __syncthreads();
        mvh<128>(wb, h1, part, tid);
        __syncthreads();
        if (tid < 128) h2[tid] = fmaxf(bh[tid] + redp(part, 128, tid), 0.f);
        __syncthreads();
        mvh<128>(wb, h2, part, tid);
        __syncthreads();
        if (tid < 128) h1[tid] = fmaxf(bh[tid] + redp(part, 128, tid), 0.f);
        __syncthreads();
        int w = tid >> 5, lane = tid & 31;
        if (w < 12) {
            const float* rw = wo + w * 128;
            float s = rw[lane] * h1[lane] + rw[lane + 32] * h1[lane + 32] +
                      rw[lane + 64] * h1[lane + 64] + rw[lane + 96] * h1[lane + 96];
#pragma unroll
            for (int d = 16; d > 0; d >>= 1) s += __shfl_xor_sync(0xffffffffu, s, d);
            if (lane == 0) { float o = sigm(s + bo[w]); dout[t * 12 + w] = o; obuf[w] = o; }
        }
        __syncthreads();
        if (t < NSTEPS - 1) {  // inline L0 for step t+1
            int np = (t + 1) & 1;
            {
                const float* wr = wih0 + tid * 13;
                float g = bias0[tid] + gc0[np * 512 + tid];
#pragma unroll
                for (int j = 0; j < 12; j++) g += wr[j] * obuf[j];
                g0[tid] = g;
            }
            __syncthreads();
            if (tid < 128) {
                float cn = sigm(g0[128 + tid]) * cS[tid] + sigm(g0[tid]) * tanhf(g0[256 + tid]);
                float hn = sigm(g0[384 + tid]) * tanhf(cn);
                cS[tid] = cn; hS[tid] = hn;
                float pv = __shfl_xor_sync(0xffffffffu, hn, 1);
                if (!(tid & 1)) {
                    unsigned o4 = XBUF + np * 512 + tid * 4;
                    st_async2(r0 + o4, hn, pv, r0 + B_BIN);
                    st_async2(r1 + o4, hn, pv, r1 + B_BIN);
                }
            }
        }
    }
    if (out_size >= 49920 && tid < 128) { dout[49152 + tid] = hS[tid]; dout[49536 + tid] = cS[tid]; }
    csync();
}

__global__ void __launch_bounds__(512, 1) __cluster_dims__(5, 1, 1) k_rnn(
    const float* Wih0, const float* Whh0, const float* bih0, const float* bhh0,
    const float* Wih1, const float* Whh1, const float* bih1, const float* bhh1,
    const float* Wih2, const float* Whh2, const float* bih2, const float* bhh2,
    const float* Wi2h, const float* Wh2h, const float* bh2h,
    const float* Wh2o, const float* bh2o, const float* out0,
    const float* h0, const float* c0, float* dout, int out_size) {
    extern __shared__ char smc[];
    unsigned sb = smem_u32(smc);
    int r = blockIdx.x, tid = threadIdx.x;
    if (r < 2)
        lstm_mid(smc, sb, 1, r, 1 - r, 2, 3, 2, 1, Wih1, Whh1, bih1, bhh1,
                 Whh0, h0, h0 + 128, c0 + 128, dout, out_size, tid);
    else if (r < 4)
        lstm_mid(smc, sb, 2, r - 2, 5 - r, 4, 4, 1, 0, Wih2, Whh2, bih2, bhh2,
                 (const float*)0, (const float*)0, h0 + 256, c0 + 256, dout, out_size, tid);
    else
        tail(smc, sb, Wih0, bih0, bhh0, Wi2h, Wh2h, bh2h, Wh2o, bh2o,
             out0, h0, c0, dout, out_size, tid);
}

extern "C" void kernel_launch(void* const* d_in, const int* in_sizes, int n_in,
                              void* d_out, int out_size) {
    const float* output0 = (const float*)d_in[1];
    const float* h0 = (const float*)d_in[2];
    const float* c0 = (const float*)d_in[3];
    const float* Wi2h = (const float*)d_in[6];
    const float* bi2h = (const float*)d_in[7];
    const float* Wh2h = (const float*)d_in[8];
    const float* bh2h = (const float*)d_in[9];
    const float* Wh2o = (const float*)d_in[10];
    const float* bh2o = (const float*)d_in[11];
    float* out = (float*)d_out;

    static int once = 0;
    if (!once) {
        cudaFuncSetAttribute(k_rnn, cudaFuncAttributeMaxDynamicSharedMemorySize, SMEMB);
        once = 1;
    }
    k_bias0<<<1, 128>>>(Wi2h, bi2h, (const float*)d_in[5]);
    k_ct<<<128, 256>>>(Wi2h, (const float*)d_in[4]);
    k_pre<<<256, 256>>>((const float*)d_in[0]);
    k_rnn<<<5, 512, SMEMB>>>(
        (const float*)d_in[12], (const float*)d_in[13], (const float*)d_in[14], (const float*)d_in[15],
        (const float*)d_in[16], (const float*)d_in[17], (const float*)d_in[18], (const float*)d_in[19],
        (const float*)d_in[20], (const float*)d_in[21], (const float*)d_in[22], (const float*)d_in[23],
        Wi2h, Wh2h, bh2h, Wh2o, bh2o, output0, h0, c0, out, out_size);
}